// round 5
// baseline (speedup 1.0000x reference)
#include <cuda_runtime.h>
#include <cstdint>

// Problem constants (match reference)
#define BB 2048
#define TT 512
#define KK 32

#define WARPS_PER_BLOCK 14
#define THREADS (WARPS_PER_BLOCK * 32)
// per-warp shared: backpointers 511*32 u8 + 128B broadcast buffer
#define BP_BYTES (511 * 32)
#define SMEM_PER_WARP (BP_BYTES + 128)
#define SMEM_TOTAL (WARPS_PER_BLOCK * SMEM_PER_WARP)

__global__ void __launch_bounds__(THREADS, 1)
crf_kernel(const float* __restrict__ pot,      // [B,T,K]
           const float* __restrict__ trans,    // [K,K]
           const int*   __restrict__ lens,     // [B]
           const int*   __restrict__ tags,     // [B,T]
           float*       __restrict__ out)      // [B*T + B + B] floats
{
    extern __shared__ unsigned char smem[];
    const int lane = threadIdx.x & 31;
    const int w    = threadIdx.x >> 5;
    const int b    = blockIdx.x * WARPS_PER_BLOCK + w;
    if (b >= BB) return;

    unsigned char* bp = smem + (size_t)w * SMEM_PER_WARP;   // [511][32] u8
    float* bc = (float*)(bp + BP_BYTES);                    // [32] broadcast buffer

    // Per-lane: column k=lane of transitions, and its exp
    float Tc[KK], Ec[KK];
#pragma unroll
    for (int j = 0; j < KK; j++) Tc[j] = trans[j * KK + lane];
#pragma unroll
    for (int j = 0; j < KK; j++) Ec[j] = __expf(Tc[j]);

    const int len = lens[b];
    const float* pb = pot + (size_t)b * TT * KK;

    float av = pb[lane];       // viterbi alpha (lane = current tag)
    float al = av;             // logsumexp alpha
    float pn = pb[KK + lane];  // prefetch t=1 (T>=2 always)

    for (int t = 1; t < len; ++t) {
        const float pc = pn;
        const int tn = (t + 1 < TT) ? (t + 1) : (TT - 1);
        pn = pb[tn * KK + lane];   // prefetch next step's potentials

        // ---- broadcast viterbi alpha through shared ----
        __syncwarp();              // protect previous iteration's reads of bc
        bc[lane] = av;
        __syncwarp();

        float v[KK];
        {
            const float4* b4 = (const float4*)bc;
#pragma unroll
            for (int q = 0; q < 8; q++) {
                float4 x = b4[q];
                v[4*q+0] = x.x + Tc[4*q+0];
                v[4*q+1] = x.y + Tc[4*q+1];
                v[4*q+2] = x.z + Tc[4*q+2];
                v[4*q+3] = x.w + Tc[4*q+3];
            }
        }
        // ---- contiguous-block tournament: max + FIRST argmax (matches jnp.argmax ties)
        int ti[KK];
#pragma unroll
        for (int j = 0; j < KK; j++) ti[j] = j;
#pragma unroll
        for (int wd = 1; wd < KK; wd <<= 1) {
#pragma unroll
            for (int i = 0; i < KK; i += 2 * wd) {
                bool p = v[i] >= v[i + wd];   // keep-left on tie -> first index
                v[i]  = p ? v[i]  : v[i + wd];
                ti[i] = p ? ti[i] : ti[i + wd];
            }
        }
        bp[(t - 1) * 32 + lane] = (unsigned char)ti[0];
        av = pc + v[0];

        // ---- logsumexp recurrence ----
        float m = al;
#pragma unroll
        for (int d = 16; d; d >>= 1)
            m = fmaxf(m, __shfl_xor_sync(0xffffffffu, m, d));
        float e = __expf(al - m);

        __syncwarp();              // protect LDS of av above before reusing bc
        bc[lane] = e;
        __syncwarp();

        float s0 = 0.f, s1 = 0.f, s2 = 0.f, s3 = 0.f;
        {
            const float4* b4 = (const float4*)bc;
#pragma unroll
            for (int q = 0; q < 8; q++) {
                float4 x = b4[q];
                s0 = fmaf(x.x, Ec[4*q+0], s0);
                s1 = fmaf(x.y, Ec[4*q+1], s1);
                s2 = fmaf(x.z, Ec[4*q+2], s2);
                s3 = fmaf(x.w, Ec[4*q+3], s3);
            }
        }
        al = pc + m + __logf((s0 + s1) + (s2 + s3));
    }

    // ---- best score + last tag (first-index argmax over lanes) ----
    float bv = av; int bi = lane;
#pragma unroll
    for (int d = 16; d; d >>= 1) {
        float ov = __shfl_xor_sync(0xffffffffu, bv, d);
        int   oi = __shfl_xor_sync(0xffffffffu, bi, d);
        if (ov > bv || (ov == bv && oi < bi)) { bv = ov; bi = oi; }
    }

    // ---- log partition ----
    float m = al;
#pragma unroll
    for (int d = 16; d; d >>= 1)
        m = fmaxf(m, __shfl_xor_sync(0xffffffffu, m, d));
    float s = __expf(al - m);
#pragma unroll
    for (int d = 16; d; d >>= 1)
        s += __shfl_xor_sync(0xffffffffu, s, d);
    const float logZ = m + __logf(s);

    // ---- sequence score of given tags (masked) ----
    const int* tgb = tags + (size_t)b * TT;
    float sc = 0.f;
#pragma unroll
    for (int i = 0; i < TT / 32; i++) {
        int t = lane + 32 * i;
        if (t < len) {
            int tg = tgb[t];
            sc += pb[t * KK + tg];
            if (t < len - 1) {
                int tg1 = tgb[t + 1];
                sc += trans[tg * KK + tg1];
            }
        }
    }
#pragma unroll
    for (int d = 16; d; d >>= 1)
        sc += __shfl_xor_sync(0xffffffffu, sc, d);

    // ---- outputs ----
    float* outTags = out + (size_t)b * TT;
    const float ltf = (float)bi;
    // tags[len-1 .. T-1] = last_tag (masked steps have identity backpointers)
    for (int i = len - 1 + lane; i < TT; i += 32) outTags[i] = ltf;

    if (lane == 0) {
        // backtrace through shared-memory backpointers
        int carry = bi;
        for (int t = len - 1; t >= 1; --t) {
            carry = bp[(t - 1) * 32 + carry];
            outTags[t - 1] = (float)carry;
        }
        out[(size_t)BB * TT + b]      = bv;         // best_score
        out[(size_t)BB * TT + BB + b] = sc - logZ;  // log_likelihood
    }
}

extern "C" void kernel_launch(void* const* d_in, const int* in_sizes, int n_in,
                              void* d_out, int out_size)
{
    const float* pot   = (const float*)d_in[0];
    const float* trans = (const float*)d_in[1];
    const int*   lens  = (const int*)d_in[2];
    const int*   tags  = (const int*)d_in[3];
    float* out = (float*)d_out;

    static bool attr_set = false;
    if (!attr_set) {
        cudaFuncSetAttribute(crf_kernel, cudaFuncAttributeMaxDynamicSharedMemorySize,
                             SMEM_TOTAL);
        attr_set = true;
    }

    const int grid = (BB + WARPS_PER_BLOCK - 1) / WARPS_PER_BLOCK; // 147
    crf_kernel<<<grid, THREADS, SMEM_TOTAL>>>(pot, trans, lens, tags, out);
}

// round 8
// speedup vs baseline: 1.2206x; 1.2206x over previous
#include <cuda_runtime.h>
#include <cstdint>

#define BB 2048
#define TT 512
#define KK 32
#define FULL 0xffffffffu

// per-block (1 warp) shared: backpointers 511*32 u8 + two 128B broadcast buffers
#define BP_BYTES (511 * 32)
#define SMEM_MAIN (BP_BYTES + 256)

__device__ int d_order[BB];

// ---- counting sort by descending length (LPT schedule) ----
__global__ void order_kernel(const int* __restrict__ lens)
{
    __shared__ int hist[512];
    __shared__ int scan[512];
    const int tid = threadIdx.x;           // 512 threads
    hist[tid] = 0;
    __syncthreads();
    for (int i = tid; i < BB; i += 512)
        atomicAdd(&hist[512 - lens[i]], 1);   // len in [1,512] -> bucket [0,511]
    __syncthreads();
    scan[tid] = hist[tid];
    __syncthreads();
    for (int off = 1; off < 512; off <<= 1) {
        int add = (tid >= off) ? scan[tid - off] : 0;
        __syncthreads();
        scan[tid] += add;
        __syncthreads();
    }
    int excl = (tid == 0) ? 0 : scan[tid - 1];
    __syncthreads();
    hist[tid] = excl;                       // reuse as running offsets
    __syncthreads();
    for (int i = tid; i < BB; i += 512) {
        int pos = atomicAdd(&hist[512 - lens[i]], 1);
        d_order[pos] = i;
    }
}

__device__ __forceinline__ unsigned long long pack2(float lo, float hi) {
    unsigned long long d;
    asm("mov.b64 %0, {%1,%2};" : "=l"(d) : "f"(lo), "f"(hi));
    return d;
}
__device__ __forceinline__ void unpack2(unsigned long long d, float& lo, float& hi) {
    asm("mov.b64 {%0,%1}, %2;" : "=f"(lo), "=f"(hi) : "l"(d));
}
__device__ __forceinline__ unsigned long long fma2(unsigned long long a,
                                                   unsigned long long b,
                                                   unsigned long long c) {
    unsigned long long d;
    asm("fma.rn.f32x2 %0, %1, %2, %3;" : "=l"(d) : "l"(a), "l"(b), "l"(c));
    return d;
}
__device__ __forceinline__ unsigned long long add2(unsigned long long a,
                                                   unsigned long long b) {
    unsigned long long d;
    asm("add.rn.f32x2 %0, %1, %2;" : "=l"(d) : "l"(a), "l"(b));
    return d;
}

__global__ void __launch_bounds__(32)
crf_kernel(const float* __restrict__ pot,      // [B,T,K]
           const float* __restrict__ trans,    // [K,K]
           const int*   __restrict__ lens,     // [B]
           const int*   __restrict__ tags,     // [B,T]
           float*       __restrict__ out)      // [B*T + B + B] floats
{
    extern __shared__ unsigned char smem[];
    unsigned char* bp = smem;                      // [511][32] u8
    float* bcV = (float*)(smem + BP_BYTES);        // [32] viterbi alpha broadcast
    float* bcE = bcV + 32;                         // [32] exp broadcast

    const int lane = threadIdx.x;
    const int b = d_order[blockIdx.x];

    // column k=lane of transitions (regs), exp(column) packed f32x2
    float Tc[KK];
#pragma unroll
    for (int j = 0; j < KK; j++) Tc[j] = trans[j * KK + lane];
    unsigned long long Ec2[KK / 2];
#pragma unroll
    for (int q = 0; q < KK / 2; q++)
        Ec2[q] = pack2(__expf(Tc[2 * q]), __expf(Tc[2 * q + 1]));

    const int len = lens[b];
    const float* pb = pot + (size_t)b * TT * KK;

    float av = pb[lane];       // viterbi alpha
    float al = av;             // logsumexp alpha
    float pn = pb[KK + lane];  // prefetch t=1

    for (int t = 1; t < len; ++t) {
        const float pc = pn;
        const int tn = (t + 1 < TT) ? (t + 1) : (TT - 1);
        pn = pb[tn * KK + lane];

        // lane-0 stabilizer (spread of al across lanes is bounded by the
        // potentials+transitions range; exp stays in f32 range)
        const float m = __shfl_sync(FULL, al, 0);
        const float e = __expf(al - m);

        __syncwarp();              // prior iteration's reads of bcV/bcE done
        bcV[lane] = av;
        bcE[lane] = e;
        __syncwarp();

        // ---- viterbi: scores + exact first-index argmax tournament ----
        float v[KK];
        {
            const float4* b4 = (const float4*)bcV;
#pragma unroll
            for (int q = 0; q < 8; q++) {
                float4 x = b4[q];
                v[4*q+0] = x.x + Tc[4*q+0];
                v[4*q+1] = x.y + Tc[4*q+1];
                v[4*q+2] = x.z + Tc[4*q+2];
                v[4*q+3] = x.w + Tc[4*q+3];
            }
        }
        int ti[KK];
#pragma unroll
        for (int j = 0; j < KK; j++) ti[j] = j;
#pragma unroll
        for (int wd = 1; wd < KK; wd <<= 1) {
#pragma unroll
            for (int i = 0; i < KK; i += 2 * wd) {
                bool p = v[i] >= v[i + wd];   // keep-left on tie -> first index
                v[i]  = p ? v[i]  : v[i + wd];
                ti[i] = p ? ti[i] : ti[i + wd];
            }
        }
        bp[(t - 1) * 32 + lane] = (unsigned char)ti[0];
        av = pc + v[0];

        // ---- logsumexp: packed f32x2 inner product with exp(transitions) ----
        unsigned long long s0 = 0ull, s1 = 0ull, s2 = 0ull, s3 = 0ull;
        {
            const ulonglong2* e2 = (const ulonglong2*)bcE;
#pragma unroll
            for (int q = 0; q < 8; q += 2) {
                ulonglong2 ya = e2[q];
                ulonglong2 yb = e2[q + 1];
                s0 = fma2(ya.x, Ec2[2*q+0], s0);
                s1 = fma2(ya.y, Ec2[2*q+1], s1);
                s2 = fma2(yb.x, Ec2[2*q+2], s2);
                s3 = fma2(yb.y, Ec2[2*q+3], s3);
            }
        }
        s0 = add2(s0, s1);
        s2 = add2(s2, s3);
        s0 = add2(s0, s2);
        float sa, sb;
        unpack2(s0, sa, sb);
        al = pc + m + __logf(sa + sb);
    }

    // ---- best score + last tag (first-index argmax over lanes) ----
    float bv = av; int bi = lane;
#pragma unroll
    for (int d = 16; d; d >>= 1) {
        float ov = __shfl_xor_sync(FULL, bv, d);
        int   oi = __shfl_xor_sync(FULL, bi, d);
        if (ov > bv || (ov == bv && oi < bi)) { bv = ov; bi = oi; }
    }

    // ---- log partition ----
    float m = al;
#pragma unroll
    for (int d = 16; d; d >>= 1)
        m = fmaxf(m, __shfl_xor_sync(FULL, m, d));
    float s = __expf(al - m);
#pragma unroll
    for (int d = 16; d; d >>= 1)
        s += __shfl_xor_sync(FULL, s, d);
    const float logZ = m + __logf(s);

    // ---- sequence score of given tags (masked) ----
    const int* tgb = tags + (size_t)b * TT;
    float sc = 0.f;
#pragma unroll
    for (int i = 0; i < TT / 32; i++) {
        int t = lane + 32 * i;
        if (t < len) {
            int tg = tgb[t];
            sc += pb[t * KK + tg];
            if (t < len - 1) {
                int tg1 = tgb[t + 1];
                sc += trans[tg * KK + tg1];
            }
        }
    }
#pragma unroll
    for (int d = 16; d; d >>= 1)
        sc += __shfl_xor_sync(FULL, sc, d);

    // ---- outputs ----
    float* outTags = out + (size_t)b * TT;
    const float ltf = (float)bi;
    for (int i = len - 1 + lane; i < TT; i += 32) outTags[i] = ltf;

    if (lane == 0) {
        int carry = bi;
        for (int t = len - 1; t >= 1; --t) {
            carry = bp[(t - 1) * 32 + carry];
            outTags[t - 1] = (float)carry;
        }
        out[(size_t)BB * TT + b]      = bv;         // best_score
        out[(size_t)BB * TT + BB + b] = sc - logZ;  // log_likelihood
    }
}

extern "C" void kernel_launch(void* const* d_in, const int* in_sizes, int n_in,
                              void* d_out, int out_size)
{
    const float* pot   = (const float*)d_in[0];
    const float* trans = (const float*)d_in[1];
    const int*   lens  = (const int*)d_in[2];
    const int*   tags  = (const int*)d_in[3];
    float* out = (float*)d_out;

    order_kernel<<<1, 512>>>(lens);
    crf_kernel<<<BB, 32, SMEM_MAIN>>>(pot, trans, lens, tags, out);
}

// round 9
// speedup vs baseline: 1.4103x; 1.1554x over previous
#include <cuda_runtime.h>
#include <cstdint>

#define BB 2048
#define TT 512
#define KK 32
#define FULL 0xffffffffu

#define WPB 4
#define THREADS (WPB * 32)
// per-warp shared: backpointers 511*32 u8 + two 128B broadcast buffers
#define BP_BYTES (511 * 32)
#define SMEM_PER_WARP (BP_BYTES + 256)
#define SMEM_TOTAL (WPB * SMEM_PER_WARP)

__device__ int d_order[BB];

// ---- counting sort by descending length (LPT schedule) ----
__global__ void order_kernel(const int* __restrict__ lens)
{
    __shared__ int hist[512];
    __shared__ int scan[512];
    const int tid = threadIdx.x;           // 512 threads
    hist[tid] = 0;
    __syncthreads();
    for (int i = tid; i < BB; i += 512)
        atomicAdd(&hist[512 - lens[i]], 1);   // len in [1,512] -> bucket [0,511]
    __syncthreads();
    scan[tid] = hist[tid];
    __syncthreads();
    for (int off = 1; off < 512; off <<= 1) {
        int add = (tid >= off) ? scan[tid - off] : 0;
        __syncthreads();
        scan[tid] += add;
        __syncthreads();
    }
    int excl = (tid == 0) ? 0 : scan[tid - 1];
    __syncthreads();
    hist[tid] = excl;                       // reuse as running offsets
    __syncthreads();
    for (int i = tid; i < BB; i += 512) {
        int pos = atomicAdd(&hist[512 - lens[i]], 1);
        d_order[pos] = i;
    }
}

__device__ __forceinline__ unsigned long long pack2(float lo, float hi) {
    unsigned long long d;
    asm("mov.b64 %0, {%1,%2};" : "=l"(d) : "f"(lo), "f"(hi));
    return d;
}
__device__ __forceinline__ void unpack2(unsigned long long d, float& lo, float& hi) {
    asm("mov.b64 {%0,%1}, %2;" : "=f"(lo), "=f"(hi) : "l"(d));
}
__device__ __forceinline__ unsigned long long fma2(unsigned long long a,
                                                   unsigned long long b,
                                                   unsigned long long c) {
    unsigned long long d;
    asm("fma.rn.f32x2 %0, %1, %2, %3;" : "=l"(d) : "l"(a), "l"(b), "l"(c));
    return d;
}
__device__ __forceinline__ unsigned long long add2(unsigned long long a,
                                                   unsigned long long b) {
    unsigned long long d;
    asm("add.rn.f32x2 %0, %1, %2;" : "=l"(d) : "l"(a), "l"(b));
    return d;
}

__global__ void __launch_bounds__(THREADS, 1)
crf_kernel(const float* __restrict__ pot,      // [B,T,K]
           const float* __restrict__ trans,    // [K,K]
           const int*   __restrict__ lens,     // [B]
           const int*   __restrict__ tags,     // [B,T]
           float*       __restrict__ out)      // [B*T + B + B] floats
{
    extern __shared__ unsigned char smem[];
    const int lane = threadIdx.x & 31;
    const int w    = threadIdx.x >> 5;

    unsigned char* bp = smem + (size_t)w * SMEM_PER_WARP;  // [511][32] u8
    float* bcV = (float*)(bp + BP_BYTES);                  // [32] viterbi alpha
    float* bcE = bcV + 32;                                 // [32] exp(al - m)

    const int b = d_order[blockIdx.x * WPB + w];

    // column k=lane of transitions (regs), exp(column) packed f32x2
    float Tc[KK];
#pragma unroll
    for (int j = 0; j < KK; j++) Tc[j] = trans[j * KK + lane];
    unsigned long long Ec2[KK / 2];
#pragma unroll
    for (int q = 0; q < KK / 2; q++)
        Ec2[q] = pack2(__expf(Tc[2 * q]), __expf(Tc[2 * q + 1]));

    const int len = lens[b];
    const float* pb = pot + (size_t)b * TT * KK;

    float av = pb[lane];       // viterbi alpha
    float al = av;             // logsumexp alpha

    // depth-4 potential prefetch pipeline (hides DRAM latency ~577 cyc)
    float p1 = pb[1 * KK + lane];
    float p2 = pb[((2 < TT) ? 2 : (TT - 1)) * KK + lane];
    float p3 = pb[((3 < TT) ? 3 : (TT - 1)) * KK + lane];
    float p4 = pb[((4 < TT) ? 4 : (TT - 1)) * KK + lane];

    for (int t = 1; t < len; ++t) {
        const float pc = p1;
        p1 = p2; p2 = p3; p3 = p4;
        const int tn = (t + 4 < TT) ? (t + 4) : (TT - 1);
        p4 = pb[tn * KK + lane];

        // lane-0 stabilizer: cross-lane alpha spread is bounded, exp stays finite
        const float m = __shfl_sync(FULL, al, 0);
        const float e = __expf(al - m);

        __syncwarp();              // prior iteration's reads of bcV/bcE done
        bcV[lane] = av;
        bcE[lane] = e;
        __syncwarp();

        // ---- viterbi: scores + exact first-index argmax tournament ----
        float v[KK];
        {
            const float4* b4 = (const float4*)bcV;
#pragma unroll
            for (int q = 0; q < 8; q++) {
                float4 x = b4[q];
                v[4*q+0] = x.x + Tc[4*q+0];
                v[4*q+1] = x.y + Tc[4*q+1];
                v[4*q+2] = x.z + Tc[4*q+2];
                v[4*q+3] = x.w + Tc[4*q+3];
            }
        }
        int ti[KK];
#pragma unroll
        for (int j = 0; j < KK; j++) ti[j] = j;
#pragma unroll
        for (int wd = 1; wd < KK; wd <<= 1) {
#pragma unroll
            for (int i = 0; i < KK; i += 2 * wd) {
                bool p = v[i] >= v[i + wd];   // keep-left on tie -> first index
                v[i]  = p ? v[i]  : v[i + wd];
                ti[i] = p ? ti[i] : ti[i + wd];
            }
        }
        bp[(t - 1) * 32 + lane] = (unsigned char)ti[0];
        av = pc + v[0];

        // ---- logsumexp: packed f32x2 inner product with exp(transitions) ----
        unsigned long long s0 = 0ull, s1 = 0ull, s2 = 0ull, s3 = 0ull;
        {
            const ulonglong2* e2 = (const ulonglong2*)bcE;
#pragma unroll
            for (int q = 0; q < 8; q += 2) {
                ulonglong2 ya = e2[q];
                ulonglong2 yb = e2[q + 1];
                s0 = fma2(ya.x, Ec2[2*q+0], s0);
                s1 = fma2(ya.y, Ec2[2*q+1], s1);
                s2 = fma2(yb.x, Ec2[2*q+2], s2);
                s3 = fma2(yb.y, Ec2[2*q+3], s3);
            }
        }
        s0 = add2(s0, s1);
        s2 = add2(s2, s3);
        s0 = add2(s0, s2);
        float sa, sb;
        unpack2(s0, sa, sb);
        al = pc + m + __logf(sa + sb);
    }

    // ---- best score + last tag (first-index argmax over lanes) ----
    float bv = av; int bi = lane;
#pragma unroll
    for (int d = 16; d; d >>= 1) {
        float ov = __shfl_xor_sync(FULL, bv, d);
        int   oi = __shfl_xor_sync(FULL, bi, d);
        if (ov > bv || (ov == bv && oi < bi)) { bv = ov; bi = oi; }
    }

    // ---- log partition ----
    float m = al;
#pragma unroll
    for (int d = 16; d; d >>= 1)
        m = fmaxf(m, __shfl_xor_sync(FULL, m, d));
    float s = __expf(al - m);
#pragma unroll
    for (int d = 16; d; d >>= 1)
        s += __shfl_xor_sync(FULL, s, d);
    const float logZ = m + __logf(s);

    // ---- sequence score of given tags (masked) ----
    const int* tgb = tags + (size_t)b * TT;
    float sc = 0.f;
#pragma unroll
    for (int i = 0; i < TT / 32; i++) {
        int t = lane + 32 * i;
        if (t < len) {
            int tg = tgb[t];
            sc += pb[t * KK + tg];
            if (t < len - 1) {
                int tg1 = tgb[t + 1];
                sc += trans[tg * KK + tg1];
            }
        }
    }
#pragma unroll
    for (int d = 16; d; d >>= 1)
        sc += __shfl_xor_sync(FULL, sc, d);

    // ---- outputs ----
    float* outTags = out + (size_t)b * TT;
    const float ltf = (float)bi;
    for (int i = len - 1 + lane; i < TT; i += 32) outTags[i] = ltf;

    if (lane == 0) {
        int carry = bi;
        for (int t = len - 1; t >= 1; --t) {
            carry = bp[(t - 1) * 32 + carry];
            outTags[t - 1] = (float)carry;
        }
        out[(size_t)BB * TT + b]      = bv;         // best_score
        out[(size_t)BB * TT + BB + b] = sc - logZ;  // log_likelihood
    }
}

extern "C" void kernel_launch(void* const* d_in, const int* in_sizes, int n_in,
                              void* d_out, int out_size)
{
    const float* pot   = (const float*)d_in[0];
    const float* trans = (const float*)d_in[1];
    const int*   lens  = (const int*)d_in[2];
    const int*   tags  = (const int*)d_in[3];
    float* out = (float*)d_out;

    static bool attr_set = false;
    if (!attr_set) {
        cudaFuncSetAttribute(crf_kernel, cudaFuncAttributeMaxDynamicSharedMemorySize,
                             SMEM_TOTAL);
        attr_set = true;
    }

    order_kernel<<<1, 512>>>(lens);
    crf_kernel<<<BB / WPB, THREADS, SMEM_TOTAL>>>(pot, trans, lens, tags, out);
}